// round 10
// baseline (speedup 1.0000x reference)
#include <cuda_runtime.h>
#include <cuda_fp16.h>
#include <mma.h>
#include <cstdint>
#include <cstring>

using namespace nvcuda;

#define B_   256
#define H_   1024
#define IN_  132
#define OUT_ 132
#define T_   100
#define G4   4096
#define INP  160     // IN_ padded to multiple of 32

#define BM   64      // rows per block (batch)
#define BNH  32      // h-columns per block
#define BN   128     // 4 gates * BNH
#define KC   32      // K chunk
#define NST  3       // pipeline stages

__device__ __forceinline__ unsigned h2_as_u32(__half2 h) {
    unsigned u;
    memcpy(&u, &h, 4);
    return u;
}

// ---------------- scratch (static device memory; no allocations) -------------
__device__ __half g_hh[2][3][B_*H_];         // ping-pong hidden states (fp16)
__device__ float  g_c[2][3][B_*H_];          // ping-pong cell states (fp32)
__device__ __half g_H2[(size_t)T_*B_*H_];    // h2 history for batched decode
__device__ __half g_xh[(size_t)T_*B_*INP];   // real_seq as [T][B][160] fp16, zero-padded
__device__ __half g_Wih1h[G4*IN_];
__device__ __half g_Whh1h[G4*H_];
__device__ __half g_Wih2h[G4*H_];
__device__ __half g_Whh2h[G4*H_];
__device__ __half g_Wih3h[G4*H_];
__device__ __half g_Whh3h[G4*H_];
__device__ __half g_Wfold[G4*H_];            // W_ih1 @ W_dec  (folded decoder)
__device__ __half g_Wdech[OUT_*H_];
__device__ float  g_biasMat[4][16*G4];       // 16-row replicated bias matrices
// packed weights: [mat][ht][kc][n(128)][k(32)]  mat: 0=Whh1 1=Wfold 2=Wih2 3=Whh2 4=Wih3 5=Whh3
__device__ __half g_Wp[6][32][32][128][32];
__device__ __half g_Wih1p[32][INP/32][128][32];

// ---------------- prologue: convert weights to fp16, zero init ---------------
__global__ void prep_kernel(const float* __restrict__ Wih1, const float* __restrict__ Whh1,
                            const float* __restrict__ Wih2, const float* __restrict__ Whh2,
                            const float* __restrict__ Wih3, const float* __restrict__ Whh3,
                            const float* __restrict__ Wdec)
{
    long i = (long)blockIdx.x * blockDim.x + threadIdx.x;
    const long NW = (long)G4 * H_;
    if (i < NW) {
        g_Whh1h[i] = __float2half(Whh1[i]);
        g_Wih2h[i] = __float2half(Wih2[i]);
        g_Whh2h[i] = __float2half(Whh2[i]);
        g_Wih3h[i] = __float2half(Wih3[i]);
        g_Whh3h[i] = __float2half(Whh3[i]);
    }
    if (i < (long)G4*IN_)   g_Wih1h[i] = __float2half(Wih1[i]);
    if (i < (long)OUT_*H_)  g_Wdech[i] = __float2half(Wdec[i]);
    if (i < (long)3*B_*H_) { (&g_hh[0][0][0])[i] = __float2half(0.f); (&g_c[0][0][0])[i] = 0.f; }
}

// ---------------- prologue: combined biases (incl. folded decoder bias) ------
__global__ void bias_kernel(const float* __restrict__ b_ih1, const float* __restrict__ b_hh1,
                            const float* __restrict__ b_ih2, const float* __restrict__ b_hh2,
                            const float* __restrict__ b_ih3, const float* __restrict__ b_hh3,
                            const float* __restrict__ b_dec, const float* __restrict__ W_ih1)
{
    int n = blockIdx.x * blockDim.x + threadIdx.x;
    if (n >= G4) return;
    float v0 = b_ih1[n] + b_hh1[n];
    float bf = 0.f;
    for (int o = 0; o < IN_; o++) bf += W_ih1[n*IN_ + o] * b_dec[o];
    float v1 = v0 + bf;                    // AR layer-1: + W_ih1 @ b_dec
    float v2 = b_ih2[n] + b_hh2[n];
    float v3 = b_ih3[n] + b_hh3[n];
    #pragma unroll
    for (int r = 0; r < 16; r++) {
        g_biasMat[0][r*G4 + n] = v0;
        g_biasMat[1][r*G4 + n] = v1;
        g_biasMat[2][r*G4 + n] = v2;
        g_biasMat[3][r*G4 + n] = v3;
    }
}

// ---------------- prologue: W_fold = W_ih1 @ W_dec  (M=4096,N=1024,K=132) ----
#define FBM 64
#define FBN 64
__global__ __launch_bounds__(128) void fold_kernel()
{
    __shared__ __align__(16) __half As[FBM][KC+8];
    __shared__ __align__(16) __half Bs[KC][FBN+8];
    __shared__ float  Cs[FBM][FBN];
    const int tid = threadIdx.x, warp = tid >> 5;
    const int m0 = blockIdx.x * FBM;
    const int n0 = blockIdx.y * FBN;

    wmma::fragment<wmma::accumulator,16,16,16,float> acc[4];
    #pragma unroll
    for (int j = 0; j < 4; j++) wmma::fill_fragment(acc[j], 0.f);

    for (int kb = 0; kb < IN_; kb += KC) {
        __syncthreads();
        #pragma unroll
        for (int i = 0; i < 16; i++) {
            int lin = i*128 + tid; int m = lin >> 5, k = lin & 31; int kg = kb + k;
            As[m][k] = (kg < IN_) ? g_Wih1h[(m0+m)*IN_ + kg] : __float2half(0.f);
        }
        #pragma unroll
        for (int i = 0; i < 16; i++) {
            int lin = i*128 + tid; int k = lin >> 6, nn = lin & 63; int kg = kb + k;
            Bs[k][nn] = (kg < IN_) ? g_Wdech[kg*H_ + n0 + nn] : __float2half(0.f);
        }
        __syncthreads();
        #pragma unroll
        for (int kk = 0; kk < KC; kk += 16) {
            wmma::fragment<wmma::matrix_a,16,16,16,__half,wmma::row_major> a;
            wmma::load_matrix_sync(a, &As[warp*16][kk], KC+8);
            #pragma unroll
            for (int j = 0; j < 4; j++) {
                wmma::fragment<wmma::matrix_b,16,16,16,__half,wmma::row_major> b;
                wmma::load_matrix_sync(b, &Bs[kk][j*16], FBN+8);
                wmma::mma_sync(acc[j], a, b, acc[j]);
            }
        }
    }
    __syncthreads();
    #pragma unroll
    for (int j = 0; j < 4; j++)
        wmma::store_matrix_sync(&Cs[warp*16][j*16], acc[j], FBN, wmma::mem_row_major);
    __syncthreads();
    #pragma unroll
    for (int i = 0; i < 32; i++) {
        int lin = i*128 + tid; int r = lin >> 6, cc = lin & 63;
        g_Wfold[(size_t)(m0+r)*H_ + n0 + cc] = __float2half(Cs[r][cc]);
    }
}

// ---------------- prologue: pack weights into blocked layout (16B tasks) -----
__global__ void pack_w_kernel()
{
    long i = (long)blockIdx.x * blockDim.x + threadIdx.x;
    const long TOT = 6L*32*32*128*4;          // 16B chunks
    if (i >= TOT) return;
    int c  = (int)(i & 3);                    // 8-half chunk within k
    int n  = (int)((i >> 2) & 127);
    int kc = (int)((i >> 9) & 31);
    int ht = (int)((i >> 14) & 31);
    int mat= (int)(i >> 19);
    int wrow = (n >> 5) * H_ + ht * 32 + (n & 31);
    long src = (long)wrow * H_ + kc * 32 + c * 8;
    const __half* S;
    switch (mat) {
        case 0: S = g_Whh1h; break;
        case 1: S = g_Wfold; break;
        case 2: S = g_Wih2h; break;
        case 3: S = g_Whh2h; break;
        case 4: S = g_Wih3h; break;
        default:S = g_Whh3h; break;
    }
    *reinterpret_cast<uint4*>(&g_Wp[mat][ht][kc][n][c*8]) =
        *reinterpret_cast<const uint4*>(S + src);
}

__global__ void pack_aux_kernel(const float* __restrict__ real_seq)
{
    long i = (long)blockIdx.x * blockDim.x + threadIdx.x;
    // pack W_ih1 (padded K=160)
    const long W1TOT = 32L*(INP/32)*128*32;
    if (i < W1TOT) {
        int k  = (int)(i & 31);
        int n  = (int)((i >> 5) & 127);
        int kc = (int)((i >> 12) % (INP/32));
        int ht = (int)(i / (32L*128*(INP/32)));
        int wrow = (n >> 5) * H_ + ht * 32 + (n & 31);
        int kg = kc*32 + k;
        g_Wih1p[ht][kc][n][k] = (kg < IN_) ? g_Wih1h[(long)wrow*IN_ + kg] : __float2half(0.f);
    }
    // pack x: [T][B][160] fp16 from [B][T][132] fp32
    const long XTOT = (long)T_*B_*INP;
    if (i < XTOT) {
        int k = (int)(i % INP);
        int b = (int)((i / INP) % B_);
        int t = (int)(i / ((long)INP*B_));
        g_xh[i] = (k < IN_) ? __float2half(real_seq[(long)b*T_*IN_ + (long)t*IN_ + k])
                            : __float2half(0.f);
    }
}

// ---------------- per-step fused kernel: 3 LSTM cells in parallel ------------
__device__ __forceinline__ void cpa16(uint32_t dst, const void* src) {
    asm volatile("cp.async.cg.shared.global [%0], [%1], 16;\n" :: "r"(dst), "l"(src));
}

__global__ __launch_bounds__(128, 4)
void step_kernel(const int* __restrict__ cond_num, const int* __restrict__ gt_num, int t)
{
    const int layer = blockIdx.z;
    const int mt    = blockIdx.x;
    const int ht    = blockIdx.y;
    const int p     = t & 1;
    const int tid   = threadIdx.x;
    const int warp  = tid >> 5;
    const int m0g   = mt * BM;

    const int gtn = __ldg(gt_num), cdn = __ldg(cond_num);
    const bool use_gt = (t % (gtn + cdn)) < gtn;

    // segment descriptors: gates = A0 @ W0p + A1 @ W1p + bias
    const __half *A0, *A1, *W0p, *W1p;
    int lda0, nc0, bvar;
    if (layer == 0) {
        A1 = g_hh[p][0] + (size_t)m0g*H_; W1p = &g_Wp[0][ht][0][0][0];
        if (use_gt) {
            A0 = g_xh + ((size_t)t*B_ + m0g)*INP; lda0 = INP; nc0 = INP/32;
            W0p = &g_Wih1p[ht][0][0][0]; bvar = 0;
        } else {
            A0 = g_hh[p][2] + (size_t)m0g*H_; lda0 = H_; nc0 = 32;
            W0p = &g_Wp[1][ht][0][0][0]; bvar = 1;
        }
    } else if (layer == 1) {
        A0 = g_hh[p][0] + (size_t)m0g*H_; W0p = &g_Wp[2][ht][0][0][0];
        A1 = g_hh[p][1] + (size_t)m0g*H_; W1p = &g_Wp[3][ht][0][0][0];
        lda0 = H_; nc0 = 32; bvar = 2;
    } else {
        A0 = g_hh[p][1] + (size_t)m0g*H_; W0p = &g_Wp[4][ht][0][0][0];
        A1 = g_hh[p][2] + (size_t)m0g*H_; W1p = &g_Wp[5][ht][0][0][0];
        lda0 = H_; nc0 = 32; bvar = 3;
    }
    const int NC = nc0 + 32;

    __shared__ __align__(16) __half As[NST][BM][KC+8];
    __shared__ __align__(16) __half Bs[NST][BN][KC+8];
    const uint32_t as_u = (uint32_t)__cvta_generic_to_shared(&As[0][0][0]);
    const uint32_t bs_u = (uint32_t)__cvta_generic_to_shared(&Bs[0][0][0]);

    // init accumulators with combined biases (16-row replicated matrix)
    wmma::fragment<wmma::accumulator,16,16,16,float> acc[8];
    #pragma unroll
    for (int j = 0; j < 8; j++) {
        int ncol = (j >> 1) * H_ + ht * BNH + (j & 1) * 16;
        wmma::load_matrix_sync(acc[j], &g_biasMat[bvar][ncol], G4, wmma::mem_row_major);
    }

    // async loader for one K-chunk into a stage
    auto load_chunk = [&](int q, int st) {
        const __half* a; const __half* w; int lda;
        if (q < nc0) { a = A0 + q*KC;        lda = lda0; w = W0p + (size_t)q*(128*32); }
        else         { a = A1 + (q-nc0)*KC;  lda = H_;   w = W1p + (size_t)(q-nc0)*(128*32); }
        #pragma unroll
        for (int j = 0; j < 2; j++) {             // A tile: 64 rows x 4 chunks of 16B
            int task = tid + j*128; int row = task >> 2, c = task & 3;
            cpa16(as_u + ((st*BM + row)*(KC+8) + c*8)*2, a + (size_t)row*lda + c*8);
        }
        #pragma unroll
        for (int j = 0; j < 4; j++) {             // W tile: 128 rows x 4 chunks of 16B
            int task = tid + j*128; int row = task >> 2, c = task & 3;
            cpa16(bs_u + ((st*BN + row)*(KC+8) + c*8)*2, w + task*8);
        }
        asm volatile("cp.async.commit_group;\n");
    };

    // 3-stage pipeline, one barrier per chunk
    load_chunk(0, 0);
    load_chunk(1, 1);
    int st = 0;
    for (int q = 0; q < NC; q++) {
        if (q + 2 < NC) {
            asm volatile("cp.async.wait_group 1;\n");
        } else {
            asm volatile("cp.async.wait_group 0;\n");
        }
        __syncthreads();
        if (q + 2 < NC) load_chunk(q + 2, (q + 2) % NST);
        #pragma unroll
        for (int kk = 0; kk < KC; kk += 16) {
            wmma::fragment<wmma::matrix_a,16,16,16,__half,wmma::row_major> a;
            wmma::load_matrix_sync(a, &As[st][warp*16][kk], KC+8);
            #pragma unroll
            for (int j = 0; j < 8; j++) {
                wmma::fragment<wmma::matrix_b,16,16,16,__half,wmma::col_major> b;
                wmma::load_matrix_sync(b, &Bs[st][j*16][kk], KC+8);
                wmma::mma_sync(acc[j], a, b, acc[j]);
            }
        }
        st = (st == NST-1) ? 0 : st + 1;
    }
    __syncthreads();   // all warps done reading smem before epilogue scratch reuse

    // epilogue: LSTM cell update fully in registers; h stored as fp16
    const int p1 = p ^ 1;
    __half*      hnew = g_hh[p1][layer];
    float*       cnew = g_c[p1][layer];
    const float* cold = g_c[p][layer];
    const int mrow = m0g + warp*16;
    const int hcol = ht * BNH;

    float* scr = reinterpret_cast<float*>(&As[0][0][0]) + warp * (16*20);
    const int lane = tid & 31;

    #pragma unroll
    for (int hf = 0; hf < 2; hf++) {
        wmma::fragment<wmma::accumulator,16,16,16,float> cfr;
        wmma::load_matrix_sync(cfr, cold + (size_t)mrow*H_ + hcol + 16*hf, H_, wmma::mem_row_major);
        wmma::fragment<wmma::accumulator,16,16,16,float>& I = acc[0+hf];
        wmma::fragment<wmma::accumulator,16,16,16,float>& F = acc[2+hf];
        wmma::fragment<wmma::accumulator,16,16,16,float>& G = acc[4+hf];
        wmma::fragment<wmma::accumulator,16,16,16,float>& O = acc[6+hf];
        #pragma unroll
        for (int e = 0; e < cfr.num_elements; e++) {
            float ii = 1.f / (1.f + __expf(-I.x[e]));
            float ff = 1.f / (1.f + __expf(-F.x[e]));
            float gg = tanhf(G.x[e]);
            float oo = 1.f / (1.f + __expf(-O.x[e]));
            float cn = ff * cfr.x[e] + ii * gg;
            cfr.x[e] = cn;
            I.x[e]   = oo * tanhf(cn);
        }
        wmma::store_matrix_sync(cnew + (size_t)mrow*H_ + hcol + 16*hf, cfr, H_, wmma::mem_row_major);
        // h (and H2 for layer 2) via per-warp smem scratch -> fp16 vector stores
        wmma::store_matrix_sync(scr, I, 20, wmma::mem_row_major);
        __syncwarp();
        {
            int r = lane >> 1, cb = (lane & 1) * 8;
            uint4 v;
            __half2 h0 = __floats2half2_rn(scr[r*20+cb+0], scr[r*20+cb+1]);
            __half2 h1 = __floats2half2_rn(scr[r*20+cb+2], scr[r*20+cb+3]);
            __half2 h2 = __floats2half2_rn(scr[r*20+cb+4], scr[r*20+cb+5]);
            __half2 h3 = __floats2half2_rn(scr[r*20+cb+6], scr[r*20+cb+7]);
            v.x = h2_as_u32(h0); v.y = h2_as_u32(h1);
            v.z = h2_as_u32(h2); v.w = h2_as_u32(h3);
            size_t off = (size_t)(mrow + r)*H_ + hcol + 16*hf + cb;
            *reinterpret_cast<uint4*>(hnew + off) = v;
            if (layer == 2)
                *reinterpret_cast<uint4*>(g_H2 + (size_t)t*(B_*H_) + off) = v;
        }
        __syncwarp();
    }
}

// ---------------- epilogue: batched decode of all 100 steps ------------------
#define DBM 64
#define DBN 144
__global__ __launch_bounds__(128)
void decode_kernel(const float* __restrict__ b_dec, float* __restrict__ out)
{
    __shared__ __align__(16) char dsm[DBM*DBN*4];
    __half (*As)[KC+8] = reinterpret_cast<__half(*)[KC+8]>(dsm);
    __half (*Bs)[KC+8] = reinterpret_cast<__half(*)[KC+8]>(dsm + DBM*(KC+8)*2);
    const int tid = threadIdx.x, warp = tid >> 5;
    const int m0 = blockIdx.x * DBM;

    wmma::fragment<wmma::accumulator,16,16,16,float> acc[9];
    #pragma unroll
    for (int j = 0; j < 9; j++) wmma::fill_fragment(acc[j], 0.f);

    for (int kb = 0; kb < H_; kb += KC) {
        __syncthreads();
        // A tile: 64 rows x 32 halfs = 256 x 16B tasks (uint4 = 8 halfs)
        #pragma unroll
        for (int i = 0; i < 2; i++) {
            int lin = i*128 + tid; int m = lin >> 2, c = lin & 3;
            *reinterpret_cast<uint4*>(&As[m][c*8]) =
                *reinterpret_cast<const uint4*>(g_H2 + (size_t)(m0+m)*H_ + kb + c*8);
        }
        #pragma unroll
        for (int i = 0; i < 36; i++) {
            int lin = i*128 + tid; int n = lin >> 5, k = lin & 31;
            Bs[n][k] = (n < OUT_) ? g_Wdech[n*H_ + kb + k] : __float2half(0.f);
        }
        __syncthreads();
        #pragma unroll
        for (int kk = 0; kk < KC; kk += 16) {
            wmma::fragment<wmma::matrix_a,16,16,16,__half,wmma::row_major> a;
            wmma::load_matrix_sync(a, &As[warp*16][kk], KC+8);
            #pragma unroll
            for (int j = 0; j < 9; j++) {
                wmma::fragment<wmma::matrix_b,16,16,16,__half,wmma::col_major> b;
                wmma::load_matrix_sync(b, &Bs[j*16][kk], KC+8);
                wmma::mma_sync(acc[j], a, b, acc[j]);
            }
        }
    }
    __syncthreads();
    float (*Cs)[DBN] = reinterpret_cast<float(*)[DBN]>(dsm);
    #pragma unroll
    for (int j = 0; j < 9; j++)
        wmma::store_matrix_sync(&Cs[warp*16][j*16], acc[j], DBN, wmma::mem_row_major);
    __syncthreads();

    for (int lin = tid; lin < DBM*OUT_; lin += 128) {
        int m = lin / OUT_, o = lin % OUT_;
        int r = m0 + m;
        int tt = r >> 8, b = r & 255;                 // r = t*256 + b
        out[(size_t)b*(T_*OUT_) + tt*OUT_ + o] = Cs[m][o] + b_dec[o];
    }
}

// -----------------------------------------------------------------------------
extern "C" void kernel_launch(void* const* d_in, const int* in_sizes, int n_in,
                              void* d_out, int out_size)
{
    const float* real_seq = (const float*)d_in[0];
    const float* W_ih1 = (const float*)d_in[1];
    const float* W_hh1 = (const float*)d_in[2];
    const float* b_ih1 = (const float*)d_in[3];
    const float* b_hh1 = (const float*)d_in[4];
    const float* W_ih2 = (const float*)d_in[5];
    const float* W_hh2 = (const float*)d_in[6];
    const float* b_ih2 = (const float*)d_in[7];
    const float* b_hh2 = (const float*)d_in[8];
    const float* W_ih3 = (const float*)d_in[9];
    const float* W_hh3 = (const float*)d_in[10];
    const float* b_ih3 = (const float*)d_in[11];
    const float* b_hh3 = (const float*)d_in[12];
    const float* W_dec = (const float*)d_in[13];
    const float* b_dec = (const float*)d_in[14];
    const int* cond_num = (const int*)d_in[15];
    const int* gt_num   = (const int*)d_in[16];
    float* out = (float*)d_out;

    // prologue: convert, biases, folded decoder, packed layouts
    const long NW = (long)G4 * H_;
    prep_kernel<<<(unsigned)((NW + 255) / 256), 256>>>(W_ih1, W_hh1, W_ih2, W_hh2,
                                                       W_ih3, W_hh3, W_dec);
    bias_kernel<<<G4/256, 256>>>(b_ih1, b_hh1, b_ih2, b_hh2, b_ih3, b_hh3, b_dec, W_ih1);
    fold_kernel<<<dim3(G4/FBM, H_/FBN), 128>>>();
    {
        const long WTOT = 6L*32*32*128*4;      // 16B tasks
        pack_w_kernel<<<(unsigned)((WTOT + 255)/256), 256>>>();
        const long ATOT = (long)T_*B_*INP;     // > W1TOT
        pack_aux_kernel<<<(unsigned)((ATOT + 255)/256), 256>>>(real_seq);
    }

    // 100 recurrence steps, one fused kernel each (3 layers in parallel)
    dim3 sgrid(B_/BM, H_/BNH, 3);
    for (int t = 0; t < T_; t++)
        step_kernel<<<sgrid, 128>>>(cond_num, gt_num, t);

    // batched decode of all timesteps
    decode_kernel<<<(T_*B_)/DBM, 128>>>(b_dec, out);
}

// round 12
// speedup vs baseline: 1.1177x; 1.1177x over previous
#include <cuda_runtime.h>
#include <cuda_fp16.h>
#include <mma.h>
#include <cstdint>
#include <cstring>

using namespace nvcuda;

#define B_   256
#define H_   1024
#define IN_  132
#define OUT_ 132
#define T_   100
#define G4   4096
#define INP  160     // IN_ padded to multiple of 32

#define BM   64      // rows per block (batch)
#define BNH  32      // h-columns per block
#define BN   128     // 4 gates * BNH
#define KC   32      // K chunk
#define NST  3       // pipeline stages
#define CP   132     // epilogue gate-tile pitch (floats)

__device__ __forceinline__ unsigned h2_as_u32(__half2 h) {
    unsigned u;
    memcpy(&u, &h, 4);
    return u;
}

// ---------------- scratch (static device memory; no allocations) -------------
__device__ __half g_hh[2][3][B_*H_];         // ping-pong hidden states (fp16)
__device__ float  g_c[2][3][B_*H_];          // ping-pong cell states (fp32)
__device__ __half g_H2[(size_t)T_*B_*H_];    // h2 history for batched decode
__device__ __half g_xh[(size_t)T_*B_*INP];   // real_seq as [T][B][160] fp16, zero-padded
__device__ __half g_Wih1h[G4*IN_];
__device__ __half g_Whh1h[G4*H_];
__device__ __half g_Wih2h[G4*H_];
__device__ __half g_Whh2h[G4*H_];
__device__ __half g_Wih3h[G4*H_];
__device__ __half g_Whh3h[G4*H_];
__device__ __half g_Wfold[G4*H_];            // W_ih1 @ W_dec  (folded decoder)
__device__ __half g_Wdech[OUT_*H_];
__device__ float  g_bias[4][G4];             // combined bias vectors
// packed weights: [mat][ht][kc][n(128)][k(32)]  mat: 0=Whh1 1=Wfold 2=Wih2 3=Whh2 4=Wih3 5=Whh3
__device__ __half g_Wp[6][32][32][128][32];
__device__ __half g_Wih1p[32][INP/32][128][32];

// ---------------- prologue: convert weights to fp16, zero init ---------------
__global__ void prep_kernel(const float* __restrict__ Wih1, const float* __restrict__ Whh1,
                            const float* __restrict__ Wih2, const float* __restrict__ Whh2,
                            const float* __restrict__ Wih3, const float* __restrict__ Whh3,
                            const float* __restrict__ Wdec)
{
    long i = (long)blockIdx.x * blockDim.x + threadIdx.x;
    const long NW = (long)G4 * H_;
    if (i < NW) {
        g_Whh1h[i] = __float2half(Whh1[i]);
        g_Wih2h[i] = __float2half(Wih2[i]);
        g_Whh2h[i] = __float2half(Whh2[i]);
        g_Wih3h[i] = __float2half(Wih3[i]);
        g_Whh3h[i] = __float2half(Whh3[i]);
    }
    if (i < (long)G4*IN_)   g_Wih1h[i] = __float2half(Wih1[i]);
    if (i < (long)OUT_*H_)  g_Wdech[i] = __float2half(Wdec[i]);
    if (i < (long)3*B_*H_) { (&g_hh[0][0][0])[i] = __float2half(0.f); (&g_c[0][0][0])[i] = 0.f; }
}

// ---------------- prologue: combined biases (incl. folded decoder bias) ------
__global__ void bias_kernel(const float* __restrict__ b_ih1, const float* __restrict__ b_hh1,
                            const float* __restrict__ b_ih2, const float* __restrict__ b_hh2,
                            const float* __restrict__ b_ih3, const float* __restrict__ b_hh3,
                            const float* __restrict__ b_dec, const float* __restrict__ W_ih1)
{
    int n = blockIdx.x * blockDim.x + threadIdx.x;
    if (n >= G4) return;
    float v0 = b_ih1[n] + b_hh1[n];
    float bf = 0.f;
    for (int o = 0; o < IN_; o++) bf += W_ih1[n*IN_ + o] * b_dec[o];
    g_bias[0][n] = v0;
    g_bias[1][n] = v0 + bf;                 // AR layer-1: + W_ih1 @ b_dec
    g_bias[2][n] = b_ih2[n] + b_hh2[n];
    g_bias[3][n] = b_ih3[n] + b_hh3[n];
}

// ---------------- prologue: W_fold = W_ih1 @ W_dec  (M=4096,N=1024,K=132) ----
#define FBM 64
#define FBN 64
__global__ __launch_bounds__(128) void fold_kernel()
{
    __shared__ __align__(16) __half As[FBM][KC+8];
    __shared__ __align__(16) __half Bs[KC][FBN+8];
    __shared__ float  Cs[FBM][FBN];
    const int tid = threadIdx.x, warp = tid >> 5;
    const int m0 = blockIdx.x * FBM;
    const int n0 = blockIdx.y * FBN;

    wmma::fragment<wmma::accumulator,16,16,16,float> acc[4];
    #pragma unroll
    for (int j = 0; j < 4; j++) wmma::fill_fragment(acc[j], 0.f);

    for (int kb = 0; kb < IN_; kb += KC) {
        __syncthreads();
        #pragma unroll
        for (int i = 0; i < 16; i++) {
            int lin = i*128 + tid; int m = lin >> 5, k = lin & 31; int kg = kb + k;
            As[m][k] = (kg < IN_) ? g_Wih1h[(m0+m)*IN_ + kg] : __float2half(0.f);
        }
        #pragma unroll
        for (int i = 0; i < 16; i++) {
            int lin = i*128 + tid; int k = lin >> 6, nn = lin & 63; int kg = kb + k;
            Bs[k][nn] = (kg < IN_) ? g_Wdech[kg*H_ + n0 + nn] : __float2half(0.f);
        }
        __syncthreads();
        #pragma unroll
        for (int kk = 0; kk < KC; kk += 16) {
            wmma::fragment<wmma::matrix_a,16,16,16,__half,wmma::row_major> a;
            wmma::load_matrix_sync(a, &As[warp*16][kk], KC+8);
            #pragma unroll
            for (int j = 0; j < 4; j++) {
                wmma::fragment<wmma::matrix_b,16,16,16,__half,wmma::row_major> b;
                wmma::load_matrix_sync(b, &Bs[kk][j*16], FBN+8);
                wmma::mma_sync(acc[j], a, b, acc[j]);
            }
        }
    }
    __syncthreads();
    #pragma unroll
    for (int j = 0; j < 4; j++)
        wmma::store_matrix_sync(&Cs[warp*16][j*16], acc[j], FBN, wmma::mem_row_major);
    __syncthreads();
    #pragma unroll
    for (int i = 0; i < 32; i++) {
        int lin = i*128 + tid; int r = lin >> 6, cc = lin & 63;
        g_Wfold[(size_t)(m0+r)*H_ + n0 + cc] = __float2half(Cs[r][cc]);
    }
}

// ---------------- prologue: pack weights into blocked layout (16B tasks) -----
__global__ void pack_w_kernel()
{
    long i = (long)blockIdx.x * blockDim.x + threadIdx.x;
    const long TOT = 6L*32*32*128*4;          // 16B chunks
    if (i >= TOT) return;
    int c  = (int)(i & 3);                    // 8-half chunk within k
    int n  = (int)((i >> 2) & 127);
    int kc = (int)((i >> 9) & 31);
    int ht = (int)((i >> 14) & 31);
    int mat= (int)(i >> 19);
    int wrow = (n >> 5) * H_ + ht * 32 + (n & 31);
    long src = (long)wrow * H_ + kc * 32 + c * 8;
    const __half* S;
    switch (mat) {
        case 0: S = g_Whh1h; break;
        case 1: S = g_Wfold; break;
        case 2: S = g_Wih2h; break;
        case 3: S = g_Whh2h; break;
        case 4: S = g_Wih3h; break;
        default:S = g_Whh3h; break;
    }
    *reinterpret_cast<uint4*>(&g_Wp[mat][ht][kc][n][c*8]) =
        *reinterpret_cast<const uint4*>(S + src);
}

__global__ void pack_aux_kernel(const float* __restrict__ real_seq)
{
    long i = (long)blockIdx.x * blockDim.x + threadIdx.x;
    // pack W_ih1 (padded K=160)
    const long W1TOT = 32L*(INP/32)*128*32;
    if (i < W1TOT) {
        int k  = (int)(i & 31);
        int n  = (int)((i >> 5) & 127);
        int kc = (int)((i >> 12) % (INP/32));
        int ht = (int)(i / (32L*128*(INP/32)));
        int wrow = (n >> 5) * H_ + ht * 32 + (n & 31);
        int kg = kc*32 + k;
        g_Wih1p[ht][kc][n][k] = (kg < IN_) ? g_Wih1h[(long)wrow*IN_ + kg] : __float2half(0.f);
    }
    // pack x: [T][B][160] fp16 from [B][T][132] fp32
    const long XTOT = (long)T_*B_*INP;
    if (i < XTOT) {
        int k = (int)(i % INP);
        int b = (int)((i / INP) % B_);
        int t = (int)(i / ((long)INP*B_));
        g_xh[i] = (k < IN_) ? __float2half(real_seq[(long)b*T_*IN_ + (long)t*IN_ + k])
                            : __float2half(0.f);
    }
}

// ---------------- per-step fused kernel: 3 LSTM cells in parallel ------------
__device__ __forceinline__ void cpa16(uint32_t dst, const void* src) {
    asm volatile("cp.async.cg.shared.global [%0], [%1], 16;\n" :: "r"(dst), "l"(src));
}

__global__ __launch_bounds__(128, 4)
void step_kernel(const int* __restrict__ cond_num, const int* __restrict__ gt_num, int t)
{
    const int layer = blockIdx.z;
    const int mt    = blockIdx.x;
    const int ht    = blockIdx.y;
    const int p     = t & 1;
    const int tid   = threadIdx.x;
    const int warp  = tid >> 5;
    const int m0g   = mt * BM;

    const int gtn = __ldg(gt_num), cdn = __ldg(cond_num);
    const bool use_gt = (t % (gtn + cdn)) < gtn;

    // segment descriptors: gates = A0 @ W0p + A1 @ W1p + bias
    const __half *A0, *A1, *W0p, *W1p;
    int lda0, nc0, bvar;
    if (layer == 0) {
        A1 = g_hh[p][0] + (size_t)m0g*H_; W1p = &g_Wp[0][ht][0][0][0];
        if (use_gt) {
            A0 = g_xh + ((size_t)t*B_ + m0g)*INP; lda0 = INP; nc0 = INP/32;
            W0p = &g_Wih1p[ht][0][0][0]; bvar = 0;
        } else {
            A0 = g_hh[p][2] + (size_t)m0g*H_; lda0 = H_; nc0 = 32;
            W0p = &g_Wp[1][ht][0][0][0]; bvar = 1;
        }
    } else if (layer == 1) {
        A0 = g_hh[p][0] + (size_t)m0g*H_; W0p = &g_Wp[2][ht][0][0][0];
        A1 = g_hh[p][1] + (size_t)m0g*H_; W1p = &g_Wp[3][ht][0][0][0];
        lda0 = H_; nc0 = 32; bvar = 2;
    } else {
        A0 = g_hh[p][1] + (size_t)m0g*H_; W0p = &g_Wp[4][ht][0][0][0];
        A1 = g_hh[p][2] + (size_t)m0g*H_; W1p = &g_Wp[5][ht][0][0][0];
        lda0 = H_; nc0 = 32; bvar = 3;
    }
    const int NC = nc0 + 32;

    __shared__ __align__(16) __half As[NST][BM][KC+8];
    __shared__ __align__(16) __half Bs[NST][BN][KC+8];
    __shared__ float bias_s[BN];
    const uint32_t as_u = (uint32_t)__cvta_generic_to_shared(&As[0][0][0]);
    const uint32_t bs_u = (uint32_t)__cvta_generic_to_shared(&Bs[0][0][0]);

    // combined bias for this block's 128 gate-columns
    {
        int gate = tid >> 5, loc = tid & 31;
        bias_s[tid] = g_bias[bvar][gate*H_ + ht*BNH + loc];
    }

    // 2x2 warp tiling: warp (wm, wn) computes rows [wm*32,+32) x cols [wn*64,+64)
    const int wm = warp & 1, wn = warp >> 1;
    wmma::fragment<wmma::accumulator,16,16,16,float> acc[2][4];
    #pragma unroll
    for (int mi = 0; mi < 2; mi++)
        #pragma unroll
        for (int nj = 0; nj < 4; nj++)
            wmma::fill_fragment(acc[mi][nj], 0.f);

    // async loader for one K-chunk into a stage
    auto load_chunk = [&](int q, int st) {
        const __half* a; const __half* w; int lda;
        if (q < nc0) { a = A0 + q*KC;        lda = lda0; w = W0p + (size_t)q*(128*32); }
        else         { a = A1 + (q-nc0)*KC;  lda = H_;   w = W1p + (size_t)(q-nc0)*(128*32); }
        #pragma unroll
        for (int j = 0; j < 2; j++) {             // A tile: 64 rows x 4 chunks of 16B
            int task = tid + j*128; int row = task >> 2, c = task & 3;
            cpa16(as_u + ((st*BM + row)*(KC+8) + c*8)*2, a + (size_t)row*lda + c*8);
        }
        #pragma unroll
        for (int j = 0; j < 4; j++) {             // W tile: 128 rows x 4 chunks of 16B
            int task = tid + j*128; int row = task >> 2, c = task & 3;
            cpa16(bs_u + ((st*BN + row)*(KC+8) + c*8)*2, w + task*8);
        }
        asm volatile("cp.async.commit_group;\n");
    };

    // 3-stage pipeline, one barrier per chunk
    load_chunk(0, 0);
    load_chunk(1, 1);
    int st = 0;
    for (int q = 0; q < NC; q++) {
        if (q + 2 < NC) {
            asm volatile("cp.async.wait_group 1;\n");
        } else {
            asm volatile("cp.async.wait_group 0;\n");
        }
        __syncthreads();
        if (q + 2 < NC) load_chunk(q + 2, (q + 2) % NST);
        #pragma unroll
        for (int kk = 0; kk < KC; kk += 16) {
            wmma::fragment<wmma::matrix_a,16,16,16,__half,wmma::row_major> a[2];
            #pragma unroll
            for (int mi = 0; mi < 2; mi++)
                wmma::load_matrix_sync(a[mi], &As[st][wm*32 + mi*16][kk], KC+8);
            #pragma unroll
            for (int nj = 0; nj < 4; nj++) {
                wmma::fragment<wmma::matrix_b,16,16,16,__half,wmma::col_major> b;
                wmma::load_matrix_sync(b, &Bs[st][wn*64 + nj*16][kk], KC+8);
                #pragma unroll
                for (int mi = 0; mi < 2; mi++)
                    wmma::mma_sync(acc[mi][nj], a[mi], b, acc[mi][nj]);
            }
        }
        st = (st == NST-1) ? 0 : st + 1;
    }
    __syncthreads();   // all warps done reading smem before gate-tile reuse

    // ---- epilogue: gate tile -> smem, then per-thread LSTM cell update ------
    float (*Cs)[CP] = reinterpret_cast<float(*)[CP]>(&As[0][0][0]);   // 64 x 132 f32
    #pragma unroll
    for (int mi = 0; mi < 2; mi++)
        #pragma unroll
        for (int nj = 0; nj < 4; nj++)
            wmma::store_matrix_sync(&Cs[wm*32 + mi*16][wn*64 + nj*16],
                                    acc[mi][nj], CP, wmma::mem_row_major);
    __syncthreads();

    const int p1 = p ^ 1;
    const int r    = tid >> 1;                 // local batch row 0..63
    const int hc0  = (tid & 1) * 16;           // h-col offset 0 or 16
    const int grow = m0g + r;
    const float* cold = &g_c[p][layer][(size_t)grow*H_ + ht*BNH + hc0];
    float*       cnew = &g_c[p1][layer][(size_t)grow*H_ + ht*BNH + hc0];
    __half*      hnew = &g_hh[p1][layer][(size_t)grow*H_ + ht*BNH + hc0];
    __half*      h2p  = &g_H2[(size_t)t*(B_*H_) + (size_t)grow*H_ + ht*BNH + hc0];

    #pragma unroll
    for (int e4 = 0; e4 < 16; e4 += 4) {
        float4 c4 = *reinterpret_cast<const float4*>(cold + e4);
        float co[4] = {c4.x, c4.y, c4.z, c4.w};
        float hv[4], cv[4];
        #pragma unroll
        for (int u = 0; u < 4; u++) {
            int hc = hc0 + e4 + u;
            float gi = Cs[r][hc]      + bias_s[hc];
            float gf = Cs[r][32+hc]   + bias_s[32+hc];
            float gg = Cs[r][64+hc]   + bias_s[64+hc];
            float go = Cs[r][96+hc]   + bias_s[96+hc];
            float ii = 1.f / (1.f + __expf(-gi));
            float ff = 1.f / (1.f + __expf(-gf));
            float g2 = tanhf(gg);
            float oo = 1.f / (1.f + __expf(-go));
            float cn = ff * co[u] + ii * g2;
            cv[u] = cn;
            hv[u] = oo * tanhf(cn);
        }
        *reinterpret_cast<float4*>(cnew + e4) = make_float4(cv[0], cv[1], cv[2], cv[3]);
        uint2 v;
        v.x = h2_as_u32(__floats2half2_rn(hv[0], hv[1]));
        v.y = h2_as_u32(__floats2half2_rn(hv[2], hv[3]));
        *reinterpret_cast<uint2*>(hnew + e4) = v;
        if (layer == 2)
            *reinterpret_cast<uint2*>(h2p + e4) = v;
    }
}

// ---------------- epilogue: batched decode of all 100 steps ------------------
#define DBM 64
#define DBN 144
__global__ __launch_bounds__(128)
void decode_kernel(const float* __restrict__ b_dec, float* __restrict__ out)
{
    __shared__ __align__(16) char dsm[DBM*DBN*4];
    __half (*As)[KC+8] = reinterpret_cast<__half(*)[KC+8]>(dsm);
    __half (*Bs)[KC+8] = reinterpret_cast<__half(*)[KC+8]>(dsm + DBM*(KC+8)*2);
    const int tid = threadIdx.x, warp = tid >> 5;
    const int m0 = blockIdx.x * DBM;

    wmma::fragment<wmma::accumulator,16,16,16,float> acc[9];
    #pragma unroll
    for (int j = 0; j < 9; j++) wmma::fill_fragment(acc[j], 0.f);

    for (int kb = 0; kb < H_; kb += KC) {
        __syncthreads();
        // A tile: 64 rows x 32 halfs = 256 x 16B tasks (uint4 = 8 halfs)
        #pragma unroll
        for (int i = 0; i < 2; i++) {
            int lin = i*128 + tid; int m = lin >> 2, c = lin & 3;
            *reinterpret_cast<uint4*>(&As[m][c*8]) =
                *reinterpret_cast<const uint4*>(g_H2 + (size_t)(m0+m)*H_ + kb + c*8);
        }
        #pragma unroll
        for (int i = 0; i < 36; i++) {
            int lin = i*128 + tid; int n = lin >> 5, k = lin & 31;
            Bs[n][k] = (n < OUT_) ? g_Wdech[n*H_ + kb + k] : __float2half(0.f);
        }
        __syncthreads();
        #pragma unroll
        for (int kk = 0; kk < KC; kk += 16) {
            wmma::fragment<wmma::matrix_a,16,16,16,__half,wmma::row_major> a;
            wmma::load_matrix_sync(a, &As[warp*16][kk], KC+8);
            #pragma unroll
            for (int j = 0; j < 9; j++) {
                wmma::fragment<wmma::matrix_b,16,16,16,__half,wmma::col_major> b;
                wmma::load_matrix_sync(b, &Bs[j*16][kk], KC+8);
                wmma::mma_sync(acc[j], a, b, acc[j]);
            }
        }
    }
    __syncthreads();
    float (*Cs)[DBN] = reinterpret_cast<float(*)[DBN]>(dsm);
    #pragma unroll
    for (int j = 0; j < 9; j++)
        wmma::store_matrix_sync(&Cs[warp*16][j*16], acc[j], DBN, wmma::mem_row_major);
    __syncthreads();

    for (int lin = tid; lin < DBM*OUT_; lin += 128) {
        int m = lin / OUT_, o = lin % OUT_;
        int r = m0 + m;
        int tt = r >> 8, b = r & 255;                 // r = t*256 + b
        out[(size_t)b*(T_*OUT_) + tt*OUT_ + o] = Cs[m][o] + b_dec[o];
    }
}

// -----------------------------------------------------------------------------
extern "C" void kernel_launch(void* const* d_in, const int* in_sizes, int n_in,
                              void* d_out, int out_size)
{
    const float* real_seq = (const float*)d_in[0];
    const float* W_ih1 = (const float*)d_in[1];
    const float* W_hh1 = (const float*)d_in[2];
    const float* b_ih1 = (const float*)d_in[3];
    const float* b_hh1 = (const float*)d_in[4];
    const float* W_ih2 = (const float*)d_in[5];
    const float* W_hh2 = (const float*)d_in[6];
    const float* b_ih2 = (const float*)d_in[7];
    const float* b_hh2 = (const float*)d_in[8];
    const float* W_ih3 = (const float*)d_in[9];
    const float* W_hh3 = (const float*)d_in[10];
    const float* b_ih3 = (const float*)d_in[11];
    const float* b_hh3 = (const float*)d_in[12];
    const float* W_dec = (const float*)d_in[13];
    const float* b_dec = (const float*)d_in[14];
    const int* cond_num = (const int*)d_in[15];
    const int* gt_num   = (const int*)d_in[16];
    float* out = (float*)d_out;

    // prologue: convert, biases, folded decoder, packed layouts
    const long NW = (long)G4 * H_;
    prep_kernel<<<(unsigned)((NW + 255) / 256), 256>>>(W_ih1, W_hh1, W_ih2, W_hh2,
                                                       W_ih3, W_hh3, W_dec);
    bias_kernel<<<G4/256, 256>>>(b_ih1, b_hh1, b_ih2, b_hh2, b_ih3, b_hh3, b_dec, W_ih1);
    fold_kernel<<<dim3(G4/FBM, H_/FBN), 128>>>();
    {
        const long WTOT = 6L*32*32*128*4;      // 16B tasks
        pack_w_kernel<<<(unsigned)((WTOT + 255)/256), 256>>>();
        const long ATOT = (long)T_*B_*INP;     // > W1TOT
        pack_aux_kernel<<<(unsigned)((ATOT + 255)/256), 256>>>(real_seq);
    }

    // 100 recurrence steps, one fused kernel each (3 layers in parallel)
    dim3 sgrid(B_/BM, H_/BNH, 3);
    for (int t = 0; t < T_; t++)
        step_kernel<<<sgrid, 128>>>(cond_num, gt_num, t);

    // batched decode of all timesteps
    decode_kernel<<<(T_*B_)/DBM, 128>>>(b_dec, out);
}